// round 1
// baseline (speedup 1.0000x reference)
#include <cuda_runtime.h>
#include <math.h>

#define NN 50000
#define EE 800000
#define ET 850000   // EE + NN self loops

// ---------------- scratch (static device allocations only) ----------------
__device__ float g_xlxr[(size_t)NN * 256];   // conv1: [N, 0:128)=xl, [128:256)=xr
__device__ float g_h1[(size_t)NN * 128];
__device__ float g_h2[(size_t)NN * 128];
__device__ float g_hlr[(size_t)NN * 32];     // conv2: [0:16)=xl2, [16:32)=xr2
__device__ int   g_deg[NN];
__device__ int   g_rowptr[NN + 1];
__device__ int   g_cursor[NN];
__device__ int   g_csr[ET];
__device__ int   g_is64;

__device__ __forceinline__ float lrelu(float x) { return x > 0.f ? x : 0.2f * x; }
__device__ __forceinline__ float elu1 (float x) { return x > 0.f ? x : expm1f(x); }

// ---------------- edge-index dtype detection (int32 vs int64) -------------
__global__ void detect_dtype(const void* ei) {
    __shared__ int cnt;
    if (threadIdx.x == 0) cnt = 0;
    __syncthreads();
    const unsigned* p = (const unsigned*)ei;
    int nz = 0;
    for (int i = threadIdx.x; i < 2048; i += 256)
        if (p[2 * i + 1] != 0u) nz++;
    if (nz) atomicAdd(&cnt, nz);
    __syncthreads();
    if (threadIdx.x == 0) g_is64 = (cnt < 8) ? 1 : 0;
}

__device__ __forceinline__ int edge_val(const void* ei, int idx, int is64) {
    if (is64) return (int)((const long long*)ei)[idx];
    return ((const int*)ei)[idx];
}

// ---------------- CSR build ----------------
__global__ void init_deg() {
    int i = blockIdx.x * blockDim.x + threadIdx.x;
    if (i < NN) g_deg[i] = 1;   // self loop
}

__global__ void degree_k(const void* ei) {
    int i = blockIdx.x * blockDim.x + threadIdx.x;
    if (i >= EE) return;
    int is64 = g_is64;
    int dst = edge_val(ei, EE + i, is64);
    atomicAdd(&g_deg[dst], 1);
}

__global__ void scan_k() {
    __shared__ int part[1024];
    int t = threadIdx.x;
    const int CH = (NN + 1023) / 1024;
    int beg = t * CH, end = min(beg + CH, NN);
    int s = 0;
    for (int i = beg; i < end; i++) s += g_deg[i];
    part[t] = s;
    __syncthreads();
    for (int off = 1; off < 1024; off <<= 1) {
        int v = (t >= off) ? part[t - off] : 0;
        __syncthreads();
        part[t] += v;
        __syncthreads();
    }
    int run = part[t] - s;   // exclusive
    for (int i = beg; i < end; i++) { g_rowptr[i] = run; run += g_deg[i]; }
    if (t == 1023) g_rowptr[NN] = part[1023];
}

__global__ void init_csr() {
    int i = blockIdx.x * blockDim.x + threadIdx.x;
    if (i >= NN) return;
    int r = g_rowptr[i];
    g_csr[r] = i;            // self loop first
    g_cursor[i] = r + 1;
}

__global__ void scatter_k(const void* ei) {
    int i = blockIdx.x * blockDim.x + threadIdx.x;
    if (i >= EE) return;
    int is64 = g_is64;
    int s = edge_val(ei, i, is64);
    int d = edge_val(ei, EE + i, is64);
    int pos = atomicAdd(&g_cursor[d], 1);
    g_csr[pos] = s;
}

// ---------------- GEMM: C[M, grid.y*64] = A[M,128] @ B[128,*] ----------------
// 64x64 tile per 256-thread block, 4x4 register micro-tile, K=128 fixed.
// act: 0=none, 1=elu. bias may be null.
__global__ void gemm128(const float* __restrict__ A, const float* __restrict__ B,
                        float* __restrict__ C, int M, int ldb, int ldc, int coff,
                        const float* __restrict__ bias, int act) {
    __shared__ float sA[16][64];
    __shared__ float sB[16][64];
    int t  = threadIdx.x;
    int tx = t & 15, ty = t >> 4;
    int row0 = blockIdx.x * 64;
    int col0 = blockIdx.y * 64;

    float acc[4][4];
#pragma unroll
    for (int i = 0; i < 4; i++)
#pragma unroll
        for (int j = 0; j < 4; j++) acc[i][j] = 0.f;

    for (int k0 = 0; k0 < 128; k0 += 16) {
        // load A tile 64x16 (transposed into smem)
        {
            int r  = t >> 2;
            int kc = (t & 3) * 4;
            int gr = row0 + r;
            float4 v = make_float4(0.f, 0.f, 0.f, 0.f);
            if (gr < M) v = *(const float4*)&A[(size_t)gr * 128 + k0 + kc];
            sA[kc + 0][r] = v.x; sA[kc + 1][r] = v.y;
            sA[kc + 2][r] = v.z; sA[kc + 3][r] = v.w;
        }
        // load B tile 16x64
        {
            int kk = t >> 4;
            int nc = (t & 15) * 4;
            float4 v = *(const float4*)&B[(size_t)(k0 + kk) * ldb + col0 + nc];
            *(float4*)&sB[kk][nc] = v;
        }
        __syncthreads();
#pragma unroll
        for (int kk = 0; kk < 16; kk++) {
            float4 a = *(float4*)&sA[kk][ty * 4];
            float4 b = *(float4*)&sB[kk][tx * 4];
            acc[0][0] += a.x * b.x; acc[0][1] += a.x * b.y; acc[0][2] += a.x * b.z; acc[0][3] += a.x * b.w;
            acc[1][0] += a.y * b.x; acc[1][1] += a.y * b.y; acc[1][2] += a.y * b.z; acc[1][3] += a.y * b.w;
            acc[2][0] += a.z * b.x; acc[2][1] += a.z * b.y; acc[2][2] += a.z * b.z; acc[2][3] += a.z * b.w;
            acc[3][0] += a.w * b.x; acc[3][1] += a.w * b.y; acc[3][2] += a.w * b.z; acc[3][3] += a.w * b.w;
        }
        __syncthreads();
    }

#pragma unroll
    for (int i = 0; i < 4; i++) {
        int row = row0 + ty * 4 + i;
        if (row >= M) continue;
        float v[4];
#pragma unroll
        for (int j = 0; j < 4; j++) {
            float c = acc[i][j];
            if (bias) c += bias[col0 + tx * 4 + j];
            if (act == 1) c = elu1(c);
            v[j] = c;
        }
        *(float4*)&C[(size_t)row * ldc + coff + col0 + tx * 4] =
            make_float4(v[0], v[1], v[2], v[3]);
    }
}

// ---------------- conv1 aggregation: warp per node, 8-head online softmax ----
__global__ void conv1_agg(const float* __restrict__ att1, const float* __restrict__ b1) {
    int gw   = (blockIdx.x * blockDim.x + threadIdx.x) >> 5;
    int lane = threadIdx.x & 31;
    int d = gw;                                   // grid is exact: 6250*8 = 50000
    const float4 xr = *(const float4*)&g_xlxr[(size_t)d * 256 + 128 + lane * 4];
    const float4 av = *(const float4*)&att1[lane * 4]; // head=(lane>>2), ch=(lane&3)*4
    const float4 bb = *(const float4*)&b1[lane * 4];
    int beg = g_rowptr[d], end = g_rowptr[d + 1];

    float m = -INFINITY, s = 0.f;
    float ax = 0.f, ay = 0.f, az = 0.f, aw = 0.f;
    for (int j = beg; j < end; j++) {
        int src = g_csr[j];
        const float4 xl = *(const float4*)&g_xlxr[(size_t)src * 256 + lane * 4];
        float ex = lrelu(xl.x + xr.x);
        float ey = lrelu(xl.y + xr.y);
        float ez = lrelu(xl.z + xr.z);
        float ew = lrelu(xl.w + xr.w);
        float p = ex * av.x + ey * av.y + ez * av.z + ew * av.w;
        p += __shfl_xor_sync(0xffffffffu, p, 1);
        p += __shfl_xor_sync(0xffffffffu, p, 2);   // quad = one head
        float mn = fmaxf(m, p);
        float f  = __expf(m - mn);
        float w  = __expf(p - mn);
        s  = s * f + w;
        ax = ax * f + xl.x * w;
        ay = ay * f + xl.y * w;
        az = az * f + xl.z * w;
        aw = aw * f + xl.w * w;
        m = mn;
    }
    float inv = 1.f / s;
    float4 o;
    o.x = elu1(ax * inv + bb.x);
    o.y = elu1(ay * inv + bb.y);
    o.z = elu1(az * inv + bb.z);
    o.w = elu1(aw * inv + bb.w);
    *(float4*)&g_h1[(size_t)d * 128 + lane * 4] = o;
}

// ---------------- conv2 transforms: [N,32] = h @ [Wl2|Wr2] ----------------
__global__ void conv2_transform(const float* __restrict__ h,
                                const float* __restrict__ Wl2,
                                const float* __restrict__ Wr2) {
    __shared__ float sw[128 * 32];
    __shared__ float sh[8][128];
    int t = threadIdx.x;
    for (int i = t; i < 128 * 16; i += 256) {
        int k = i >> 4, c = i & 15;
        sw[k * 32 + c]      = Wl2[i];
        sw[k * 32 + 16 + c] = Wr2[i];
    }
    int row0 = blockIdx.x * 8;
    for (int i = t; i < 8 * 128; i += 256) {
        int r = i >> 7;
        sh[r][i & 127] = h[(size_t)(row0 + r) * 128 + (i & 127)];
    }
    __syncthreads();
    int warp = t >> 5, lane = t & 31;
    int row = row0 + warp;                        // exact grid: 6250*8 = 50000
    float acc = 0.f;
#pragma unroll
    for (int k = 0; k < 128; k++) acc += sh[warp][k] * sw[k * 32 + lane];
    g_hlr[(size_t)row * 32 + lane] = acc;
}

// ---------------- conv2 aggregation + log_softmax: half-warp per node ------
__global__ void conv2_agg(const float* __restrict__ att2, const float* __restrict__ b2,
                          float* __restrict__ out) {
    int tid = blockIdx.x * blockDim.x + threadIdx.x;
    int d = tid >> 4;                             // exact grid: 3125*16 = 50000
    int l = tid & 15;
    unsigned hm = 0xFFFFu << (((threadIdx.x & 31) >> 4) * 16);  // own half-warp

    float xr = g_hlr[(size_t)d * 32 + 16 + l];
    float a  = att2[l];
    int beg = g_rowptr[d], end = g_rowptr[d + 1];

    float m = -INFINITY, s = 0.f, acc = 0.f;
    for (int j = beg; j < end; j++) {
        int src = g_csr[j];
        float xl = g_hlr[(size_t)src * 32 + l];
        float p = lrelu(xl + xr) * a;
        p += __shfl_xor_sync(hm, p, 1);
        p += __shfl_xor_sync(hm, p, 2);
        p += __shfl_xor_sync(hm, p, 4);
        p += __shfl_xor_sync(hm, p, 8);
        float mn = fmaxf(m, p);
        float f  = __expf(m - mn);
        float w  = __expf(p - mn);
        s   = s * f + w;
        acc = acc * f + xl * w;
        m = mn;
    }
    float v = acc / s + b2[l];
    // log_softmax over the 16 channels (the 16 lanes of this half-warp)
    float mm = v;
#pragma unroll
    for (int k = 8; k >= 1; k >>= 1) mm = fmaxf(mm, __shfl_xor_sync(hm, mm, k));
    float pe = expf(v - mm);
    float ss = pe;
#pragma unroll
    for (int k = 8; k >= 1; k >>= 1) ss += __shfl_xor_sync(hm, ss, k);
    out[(size_t)d * 16 + l] = v - mm - logf(ss);
}

// ---------------- launch ----------------
extern "C" void kernel_launch(void* const* d_in, const int* in_sizes, int n_in,
                              void* d_out, int out_size) {
    const float* x    = (const float*)d_in[0];
    const void*  ei   = d_in[1];
    const float* Wl1  = (const float*)d_in[2];
    const float* Wr1  = (const float*)d_in[3];
    const float* att1 = (const float*)d_in[4];
    const float* b1   = (const float*)d_in[5];
    const float* Wk   = (const float*)d_in[6];
    const float* bk   = (const float*)d_in[7];
    const float* Wl2  = (const float*)d_in[8];
    const float* Wr2  = (const float*)d_in[9];
    const float* att2 = (const float*)d_in[10];
    const float* b2   = (const float*)d_in[11];
    float* out = (float*)d_out;

    float *xlxr, *h1, *h2;
    cudaGetSymbolAddress((void**)&xlxr, g_xlxr);
    cudaGetSymbolAddress((void**)&h1, g_h1);
    cudaGetSymbolAddress((void**)&h2, g_h2);

    // CSR build
    detect_dtype<<<1, 256>>>(ei);
    init_deg<<<(NN + 255) / 256, 256>>>();
    degree_k<<<(EE + 255) / 256, 256>>>(ei);
    scan_k<<<1, 1024>>>();
    init_csr<<<(NN + 255) / 256, 256>>>();
    scatter_k<<<(EE + 255) / 256, 256>>>(ei);

    // conv1 transforms: xl | xr into g_xlxr
    dim3 gx((NN + 63) / 64, 2);
    gemm128<<<gx, 256>>>(x, Wl1, xlxr, NN, 128, 256, 0,   nullptr, 0);
    gemm128<<<gx, 256>>>(x, Wr1, xlxr, NN, 128, 256, 128, nullptr, 0);

    // conv1 aggregation (+elu) -> g_h1
    conv1_agg<<<NN / 8, 256>>>(att1, b1);

    // knowledge layers (elu fused)
    gemm128<<<gx, 256>>>(h1, Wk,             h2, NN, 128, 128, 0, bk,       1);
    gemm128<<<gx, 256>>>(h2, Wk + 128 * 128, h1, NN, 128, 128, 0, bk + 128, 1);
    gemm128<<<gx, 256>>>(h1, Wk + 2 * 128 * 128, h2, NN, 128, 128, 0, bk + 256, 1);

    // conv2 transforms -> g_hlr
    conv2_transform<<<NN / 8, 256>>>(h2, Wl2, Wr2);

    // conv2 aggregation + log_softmax -> out
    conv2_agg<<<NN / 16, 256>>>(att2, b2, out);
}

// round 2
// speedup vs baseline: 1.0215x; 1.0215x over previous
#include <cuda_runtime.h>
#include <math.h>

#define NN 50000
#define EE 800000
#define ET 850000   // EE + NN self loops

// ---------------- scratch (static device allocations only) ----------------
__device__ float g_xlxr[(size_t)NN * 256];   // [0:N*128)=xl dense, [N*128:)=xr dense
__device__ float g_h1[(size_t)NN * 128];
__device__ float g_h2[(size_t)NN * 128];
__device__ float g_hlr[(size_t)NN * 32];     // conv2: [0:16)=xl2, [16:32)=xr2
__device__ int   g_deg[NN];
__device__ int   g_rowptr[NN + 1];
__device__ int   g_cursor[NN];
__device__ int   g_csr[ET];
__device__ int   g_is64;

__device__ __forceinline__ float lrelu(float x) { return x > 0.f ? x : 0.2f * x; }
__device__ __forceinline__ float elu1 (float x) { return x > 0.f ? x : expm1f(x); }

// ---------------- edge-index dtype detection (int32 vs int64) -------------
__global__ void detect_dtype(const void* ei) {
    __shared__ int cnt;
    if (threadIdx.x == 0) cnt = 0;
    __syncthreads();
    const unsigned* p = (const unsigned*)ei;
    int nz = 0;
    for (int i = threadIdx.x; i < 2048; i += 256)
        if (p[2 * i + 1] != 0u) nz++;
    if (nz) atomicAdd(&cnt, nz);
    __syncthreads();
    if (threadIdx.x == 0) g_is64 = (cnt < 8) ? 1 : 0;
}

__device__ __forceinline__ int edge_val(const void* ei, int idx, int is64) {
    if (is64) return (int)((const long long*)ei)[idx];
    return ((const int*)ei)[idx];
}

// ---------------- CSR build ----------------
__global__ void init_deg() {
    int i = blockIdx.x * blockDim.x + threadIdx.x;
    if (i < NN) g_deg[i] = 1;   // self loop
}

__global__ void degree_k(const void* ei) {
    int i = blockIdx.x * blockDim.x + threadIdx.x;
    if (i >= EE) return;
    int is64 = g_is64;
    int dst = edge_val(ei, EE + i, is64);
    atomicAdd(&g_deg[dst], 1);
}

// Streaming single-block scan, coalesced, fused with init_csr.
// rowptr[i] = exclusive prefix; g_csr[rowptr[i]] = i (self loop); cursor = +1.
__global__ void scan_fused() {
    __shared__ int warpsum[32];
    int t = threadIdx.x, lane = t & 31, w = t >> 5;
    int carry = 0;
    for (int base = 0; base < NN; base += 1024) {
        int i = base + t;
        int d = (i < NN) ? g_deg[i] : 0;
        // inclusive warp scan
        int v = d;
#pragma unroll
        for (int off = 1; off < 32; off <<= 1) {
            int u = __shfl_up_sync(0xffffffffu, v, off);
            if (lane >= off) v += u;
        }
        __syncthreads();                 // protect warpsum from previous tile
        if (lane == 31) warpsum[w] = v;
        __syncthreads();
        if (w == 0) {
            int s = warpsum[lane];
#pragma unroll
            for (int off = 1; off < 32; off <<= 1) {
                int u = __shfl_up_sync(0xffffffffu, s, off);
                if (lane >= off) s += u;
            }
            warpsum[lane] = s;           // inclusive over warps
        }
        __syncthreads();
        int incl = v + (w > 0 ? warpsum[w - 1] : 0);
        int excl = carry + incl - d;
        if (i < NN) {
            g_rowptr[i] = excl;
            g_csr[excl] = i;             // self loop first
            g_cursor[i] = excl + 1;
        }
        carry += warpsum[31];
    }
    if (t == 0) g_rowptr[NN] = carry;
}

__global__ void scatter_k(const void* ei) {
    int i = blockIdx.x * blockDim.x + threadIdx.x;
    if (i >= EE) return;
    int is64 = g_is64;
    int s = edge_val(ei, i, is64);
    int d = edge_val(ei, EE + i, is64);
    int pos = atomicAdd(&g_cursor[d], 1);
    g_csr[pos] = s;
}

// ---------------- GEMM: C[M,128] = A[M,128] @ B[128,128] ----------------
// 128x64 tile per 256-thread block, 8x4 register micro-tile, K=128 fixed.
// grid = (ceil(M/128), 2). act: 0=none, 1=elu. bias may be null.
__global__ void __launch_bounds__(256) gemm128t(
    const float* __restrict__ A, const float* __restrict__ B,
    float* __restrict__ C, int M,
    const float* __restrict__ bias, int act) {
    __shared__ float sA[16][132];
    __shared__ float sB[16][64];
    int t  = threadIdx.x;
    int tx = t & 15, ty = t >> 4;
    int row0 = blockIdx.x * 128;
    int col0 = blockIdx.y * 64;

    float acc[8][4];
#pragma unroll
    for (int i = 0; i < 8; i++)
#pragma unroll
        for (int j = 0; j < 4; j++) acc[i][j] = 0.f;

    int ar = t >> 2;            // 0..63
    int akc = (t & 3) * 4;      // 0,4,8,12
    int bkk = t >> 4;           // 0..15
    int bnc = (t & 15) * 4;     // 0..60

    for (int k0 = 0; k0 < 128; k0 += 16) {
        // A tile 128x16, transposed into sA[k][row]
#pragma unroll
        for (int h = 0; h < 2; h++) {
            int r = ar + h * 64;
            int gr = row0 + r;
            float4 v = make_float4(0.f, 0.f, 0.f, 0.f);
            if (gr < M) v = *(const float4*)&A[(size_t)gr * 128 + k0 + akc];
            sA[akc + 0][r] = v.x; sA[akc + 1][r] = v.y;
            sA[akc + 2][r] = v.z; sA[akc + 3][r] = v.w;
        }
        // B tile 16x64
        *(float4*)&sB[bkk][bnc] =
            *(const float4*)&B[(size_t)(k0 + bkk) * 128 + col0 + bnc];
        __syncthreads();
#pragma unroll
        for (int kk = 0; kk < 16; kk++) {
            float4 a0 = *(float4*)&sA[kk][ty * 8];
            float4 a1 = *(float4*)&sA[kk][ty * 8 + 4];
            float4 b  = *(float4*)&sB[kk][tx * 4];
            acc[0][0] += a0.x * b.x; acc[0][1] += a0.x * b.y; acc[0][2] += a0.x * b.z; acc[0][3] += a0.x * b.w;
            acc[1][0] += a0.y * b.x; acc[1][1] += a0.y * b.y; acc[1][2] += a0.y * b.z; acc[1][3] += a0.y * b.w;
            acc[2][0] += a0.z * b.x; acc[2][1] += a0.z * b.y; acc[2][2] += a0.z * b.z; acc[2][3] += a0.z * b.w;
            acc[3][0] += a0.w * b.x; acc[3][1] += a0.w * b.y; acc[3][2] += a0.w * b.z; acc[3][3] += a0.w * b.w;
            acc[4][0] += a1.x * b.x; acc[4][1] += a1.x * b.y; acc[4][2] += a1.x * b.z; acc[4][3] += a1.x * b.w;
            acc[5][0] += a1.y * b.x; acc[5][1] += a1.y * b.y; acc[5][2] += a1.y * b.z; acc[5][3] += a1.y * b.w;
            acc[6][0] += a1.z * b.x; acc[6][1] += a1.z * b.y; acc[6][2] += a1.z * b.z; acc[6][3] += a1.z * b.w;
            acc[7][0] += a1.w * b.x; acc[7][1] += a1.w * b.y; acc[7][2] += a1.w * b.z; acc[7][3] += a1.w * b.w;
        }
        __syncthreads();
    }

    float bv[4] = {0.f, 0.f, 0.f, 0.f};
    if (bias) {
#pragma unroll
        for (int j = 0; j < 4; j++) bv[j] = bias[col0 + tx * 4 + j];
    }
#pragma unroll
    for (int i = 0; i < 8; i++) {
        int row = row0 + ty * 8 + i;
        if (row >= M) continue;
        float v[4];
#pragma unroll
        for (int j = 0; j < 4; j++) {
            float c = acc[i][j] + bv[j];
            if (act == 1) c = elu1(c);
            v[j] = c;
        }
        *(float4*)&C[(size_t)row * 128 + col0 + tx * 4] =
            make_float4(v[0], v[1], v[2], v[3]);
    }
}

// ---------------- conv1 aggregation: warp per node, 8-head online softmax ----
__global__ void conv1_agg(const float* __restrict__ att1, const float* __restrict__ b1) {
    int gw   = (blockIdx.x * blockDim.x + threadIdx.x) >> 5;
    int lane = threadIdx.x & 31;
    int d = gw;                                   // grid exact: 6250*8 = 50000
    const float* xlbase = g_xlxr;
    const float* xrbase = g_xlxr + (size_t)NN * 128;
    const float4 xr = *(const float4*)&xrbase[(size_t)d * 128 + lane * 4];
    const float4 av = *(const float4*)&att1[lane * 4]; // head=(lane>>2), ch=(lane&3)*4
    const float4 bb = *(const float4*)&b1[lane * 4];
    int beg = g_rowptr[d], end = g_rowptr[d + 1];

    float m = -INFINITY, s = 0.f;
    float ax = 0.f, ay = 0.f, az = 0.f, aw = 0.f;

    int src = g_csr[beg];
    float4 xl = *(const float4*)&xlbase[(size_t)src * 128 + lane * 4];
    for (int j = beg; j < end; j++) {
        float4 xln;
        if (j + 1 < end) {  // prefetch next row while computing current
            int nsrc = g_csr[j + 1];
            xln = *(const float4*)&xlbase[(size_t)nsrc * 128 + lane * 4];
        }
        float ex = lrelu(xl.x + xr.x);
        float ey = lrelu(xl.y + xr.y);
        float ez = lrelu(xl.z + xr.z);
        float ew = lrelu(xl.w + xr.w);
        float p = ex * av.x + ey * av.y + ez * av.z + ew * av.w;
        p += __shfl_xor_sync(0xffffffffu, p, 1);
        p += __shfl_xor_sync(0xffffffffu, p, 2);   // quad = one head
        float mn = fmaxf(m, p);
        float f  = __expf(m - mn);
        float wt = __expf(p - mn);
        s  = s * f + wt;
        ax = ax * f + xl.x * wt;
        ay = ay * f + xl.y * wt;
        az = az * f + xl.z * wt;
        aw = aw * f + xl.w * wt;
        m = mn;
        xl = xln;
    }
    float inv = 1.f / s;
    float4 o;
    o.x = elu1(ax * inv + bb.x);
    o.y = elu1(ay * inv + bb.y);
    o.z = elu1(az * inv + bb.z);
    o.w = elu1(aw * inv + bb.w);
    *(float4*)&g_h1[(size_t)d * 128 + lane * 4] = o;
}

// ---------------- conv2 transforms: [N,32] = h @ [Wl2|Wr2] ----------------
__global__ void conv2_transform(const float* __restrict__ h,
                                const float* __restrict__ Wl2,
                                const float* __restrict__ Wr2) {
    __shared__ float sw[128 * 32];
    __shared__ float sh[8][128];
    int t = threadIdx.x;
    for (int i = t; i < 128 * 16; i += 256) {
        int k = i >> 4, c = i & 15;
        sw[k * 32 + c]      = Wl2[i];
        sw[k * 32 + 16 + c] = Wr2[i];
    }
    int row0 = blockIdx.x * 8;
    for (int i = t; i < 8 * 128; i += 256) {
        int r = i >> 7;
        sh[r][i & 127] = h[(size_t)(row0 + r) * 128 + (i & 127)];
    }
    __syncthreads();
    int warp = t >> 5, lane = t & 31;
    int row = row0 + warp;                        // exact grid: 6250*8 = 50000
    float acc = 0.f;
#pragma unroll
    for (int k = 0; k < 128; k++) acc += sh[warp][k] * sw[k * 32 + lane];
    g_hlr[(size_t)row * 32 + lane] = acc;
}

// ---------------- conv2 aggregation + log_softmax: half-warp per node ------
__global__ void conv2_agg(const float* __restrict__ att2, const float* __restrict__ b2,
                          float* __restrict__ out) {
    int tid = blockIdx.x * blockDim.x + threadIdx.x;
    int d = tid >> 4;                             // exact grid: 3125*16 = 50000
    int l = tid & 15;
    unsigned hm = 0xFFFFu << (((threadIdx.x & 31) >> 4) * 16);  // own half-warp

    float xr = g_hlr[(size_t)d * 32 + 16 + l];
    float a  = att2[l];
    int beg = g_rowptr[d], end = g_rowptr[d + 1];

    float m = -INFINITY, s = 0.f, acc = 0.f;
    int src = g_csr[beg];
    float xl = g_hlr[(size_t)src * 32 + l];
    for (int j = beg; j < end; j++) {
        float xln = 0.f;
        if (j + 1 < end) {
            int nsrc = g_csr[j + 1];
            xln = g_hlr[(size_t)nsrc * 32 + l];
        }
        float p = lrelu(xl + xr) * a;
        p += __shfl_xor_sync(hm, p, 1);
        p += __shfl_xor_sync(hm, p, 2);
        p += __shfl_xor_sync(hm, p, 4);
        p += __shfl_xor_sync(hm, p, 8);
        float mn = fmaxf(m, p);
        float f  = __expf(m - mn);
        float w  = __expf(p - mn);
        s   = s * f + w;
        acc = acc * f + xl * w;
        m = mn;
        xl = xln;
    }
    float v = acc / s + b2[l];
    // log_softmax over the 16 channels (the 16 lanes of this half-warp)
    float mm = v;
#pragma unroll
    for (int k = 8; k >= 1; k >>= 1) mm = fmaxf(mm, __shfl_xor_sync(hm, mm, k));
    float pe = expf(v - mm);
    float ss = pe;
#pragma unroll
    for (int k = 8; k >= 1; k >>= 1) ss += __shfl_xor_sync(hm, ss, k);
    out[(size_t)d * 16 + l] = v - mm - logf(ss);
}

// ---------------- launch ----------------
extern "C" void kernel_launch(void* const* d_in, const int* in_sizes, int n_in,
                              void* d_out, int out_size) {
    const float* x    = (const float*)d_in[0];
    const void*  ei   = d_in[1];
    const float* Wl1  = (const float*)d_in[2];
    const float* Wr1  = (const float*)d_in[3];
    const float* att1 = (const float*)d_in[4];
    const float* b1   = (const float*)d_in[5];
    const float* Wk   = (const float*)d_in[6];
    const float* bk   = (const float*)d_in[7];
    const float* Wl2  = (const float*)d_in[8];
    const float* Wr2  = (const float*)d_in[9];
    const float* att2 = (const float*)d_in[10];
    const float* b2   = (const float*)d_in[11];
    float* out = (float*)d_out;

    float *xlxr, *h1, *h2;
    cudaGetSymbolAddress((void**)&xlxr, g_xlxr);
    cudaGetSymbolAddress((void**)&h1, g_h1);
    cudaGetSymbolAddress((void**)&h2, g_h2);
    float* xl = xlxr;
    float* xr = xlxr + (size_t)NN * 128;

    // CSR build
    detect_dtype<<<1, 256>>>(ei);
    init_deg<<<(NN + 255) / 256, 256>>>();
    degree_k<<<(EE + 255) / 256, 256>>>(ei);
    scan_fused<<<1, 1024>>>();
    scatter_k<<<(EE + 255) / 256, 256>>>(ei);

    // conv1 transforms (dense xl / xr arrays)
    dim3 gx((NN + 127) / 128, 2);
    gemm128t<<<gx, 256>>>(x, Wl1, xl, NN, nullptr, 0);
    gemm128t<<<gx, 256>>>(x, Wr1, xr, NN, nullptr, 0);

    // conv1 aggregation (+elu) -> g_h1
    conv1_agg<<<NN / 8, 256>>>(att1, b1);

    // knowledge layers (elu fused)
    gemm128t<<<gx, 256>>>(h1, Wk,                 h2, NN, bk,       1);
    gemm128t<<<gx, 256>>>(h2, Wk + 128 * 128,     h1, NN, bk + 128, 1);
    gemm128t<<<gx, 256>>>(h1, Wk + 2 * 128 * 128, h2, NN, bk + 256, 1);

    // conv2 transforms -> g_hlr
    conv2_transform<<<NN / 8, 256>>>(h2, Wl2, Wr2);

    // conv2 aggregation + log_softmax -> out
    conv2_agg<<<NN / 16, 256>>>(att2, b2, out);
}

// round 3
// speedup vs baseline: 1.1728x; 1.1481x over previous
#include <cuda_runtime.h>
#include <math.h>

#define NN 50000
#define EE 800000
#define ET 850000   // EE + NN self loops
#define NB 196      // ceil(NN/256)

// ---------------- scratch (static device allocations only) ----------------
__device__ float g_xlxr[(size_t)NN * 256];   // [0:N*128)=xl dense, [N*128:)=xr dense
__device__ float g_h1[(size_t)NN * 128];
__device__ float g_h2[(size_t)NN * 128];
__device__ float g_hlr[(size_t)NN * 32];     // conv2: [0:16)=xl2, [16:32)=xr2
__device__ int   g_deg[NN];
__device__ int   g_rowptr[NN + 1];
__device__ int   g_cursor[NN];
__device__ int   g_csr[ET];
__device__ int   g_part[256];
__device__ int   g_is64;

__device__ __forceinline__ float lrelu(float x) { return x > 0.f ? x : 0.2f * x; }
__device__ __forceinline__ float elu1 (float x) { return x > 0.f ? x : expm1f(x); }

// ---------------- init deg=0 + dtype detect (block 0) ----------------------
__global__ void init_detect(const void* ei) {
    int i = blockIdx.x * blockDim.x + threadIdx.x;
    if (i < NN) g_deg[i] = 0;
    if (blockIdx.x == 0) {
        __shared__ int cnt;
        if (threadIdx.x == 0) cnt = 0;
        __syncthreads();
        const unsigned* p = (const unsigned*)ei;
        int nz = 0;
        for (int k = threadIdx.x; k < 2048; k += 256)
            if (p[2 * k + 1] != 0u) nz++;
        if (nz) atomicAdd(&cnt, nz);
        __syncthreads();
        if (threadIdx.x == 0) g_is64 = (cnt < 8) ? 1 : 0;
    }
}

__device__ __forceinline__ int edge_val(const void* ei, int idx, int is64) {
    if (is64) return (int)((const long long*)ei)[idx];
    return ((const int*)ei)[idx];
}

__global__ void degree_k(const void* ei) {
    int i = blockIdx.x * blockDim.x + threadIdx.x;
    if (i >= EE) return;
    int is64 = g_is64;
    int dst = edge_val(ei, EE + i, is64);
    atomicAdd(&g_deg[dst], 1);
}

// ---------------- parallel scan over (deg[i]+1) ----------------------------
__global__ void scan_part() {
    int t = threadIdx.x, lane = t & 31, w = t >> 5;
    int i = blockIdx.x * 256 + t;
    int v = (i < NN) ? g_deg[i] + 1 : 0;
#pragma unroll
    for (int off = 16; off >= 1; off >>= 1) v += __shfl_xor_sync(0xffffffffu, v, off);
    __shared__ int ws[8];
    if (lane == 0) ws[w] = v;
    __syncthreads();
    if (t == 0) {
        int s = 0;
#pragma unroll
        for (int k = 0; k < 8; k++) s += ws[k];
        g_part[blockIdx.x] = s;
    }
}

__global__ void scan_mid() {
    int t = threadIdx.x, lane = t & 31, w = t >> 5;
    int d = (t < NB) ? g_part[t] : 0;
    int v = d;
#pragma unroll
    for (int off = 1; off < 32; off <<= 1) {
        int u = __shfl_up_sync(0xffffffffu, v, off);
        if (lane >= off) v += u;
    }
    __shared__ int ws[8];
    if (lane == 31) ws[w] = v;
    __syncthreads();
    if (w == 0 && lane < 8) {
        int s = ws[lane];
#pragma unroll
        for (int off = 1; off < 8; off <<= 1) {
            int u = __shfl_up_sync(0xffu, s, off);
            if (lane >= off) s += u;
        }
        ws[lane] = s;
    }
    __syncthreads();
    int incl = v + (w > 0 ? ws[w - 1] : 0);
    if (t < NB) g_part[t] = incl - d;      // exclusive block offset
    if (t == 255) g_rowptr[NN] = incl;     // total (zeros beyond NB)
}

__global__ void scan_add() {
    int t = threadIdx.x, lane = t & 31, w = t >> 5;
    int i = blockIdx.x * 256 + t;
    int d = (i < NN) ? g_deg[i] + 1 : 0;
    int v = d;
#pragma unroll
    for (int off = 1; off < 32; off <<= 1) {
        int u = __shfl_up_sync(0xffffffffu, v, off);
        if (lane >= off) v += u;
    }
    __shared__ int ws[8];
    if (lane == 31) ws[w] = v;
    __syncthreads();
    if (w == 0 && lane < 8) {
        int s = ws[lane];
#pragma unroll
        for (int off = 1; off < 8; off <<= 1) {
            int u = __shfl_up_sync(0xffu, s, off);
            if (lane >= off) s += u;
        }
        ws[lane] = s;
    }
    __syncthreads();
    int excl = g_part[blockIdx.x] + v - d + (w > 0 ? ws[w - 1] : 0);
    if (i < NN) {
        g_rowptr[i] = excl;
        g_csr[excl] = i;          // self loop first
        g_cursor[i] = excl + 1;
    }
}

__global__ void scatter_k(const void* ei) {
    int i = blockIdx.x * blockDim.x + threadIdx.x;
    if (i >= EE) return;
    int is64 = g_is64;
    int s = edge_val(ei, i, is64);
    int d = edge_val(ei, EE + i, is64);
    int pos = atomicAdd(&g_cursor[d], 1);
    g_csr[pos] = s;
}

// ---------------- GEMM: C[M,128] = A[M,128] @ B[128,128] -------------------
// 128x64 tile, 256 threads, 8x4 micro-tile, K=128, software-pipelined
// double-buffered smem. grid=(ceil(M/128), 2). act: 0=none, 1=elu.
__global__ void __launch_bounds__(256) gemm128t(
    const float* __restrict__ A, const float* __restrict__ B,
    float* __restrict__ C, int M,
    const float* __restrict__ bias, int act) {
    __shared__ float sA[2][16][132];
    __shared__ float sB[2][16][64];
    int t  = threadIdx.x;
    int tx = t & 15, ty = t >> 4;
    int row0 = blockIdx.x * 128;
    int col0 = blockIdx.y * 64;

    int ar  = t >> 2;            // 0..63
    int akc = (t & 3) * 4;       // 0,4,8,12
    int bkk = t >> 4;            // 0..15
    int bnc = (t & 15) * 4;      // 0..60

    float acc[8][4];
#pragma unroll
    for (int i = 0; i < 8; i++)
#pragma unroll
        for (int j = 0; j < 4; j++) acc[i][j] = 0.f;

    float4 pa0, pa1, pb;
    int gr0 = row0 + ar, gr1 = row0 + ar + 64;

    // prologue: tile 0
    pa0 = (gr0 < M) ? *(const float4*)&A[(size_t)gr0 * 128 + akc] : make_float4(0, 0, 0, 0);
    pa1 = (gr1 < M) ? *(const float4*)&A[(size_t)gr1 * 128 + akc] : make_float4(0, 0, 0, 0);
    pb  = *(const float4*)&B[(size_t)bkk * 128 + col0 + bnc];
    {
        sA[0][akc + 0][ar] = pa0.x; sA[0][akc + 1][ar] = pa0.y;
        sA[0][akc + 2][ar] = pa0.z; sA[0][akc + 3][ar] = pa0.w;
        sA[0][akc + 0][ar + 64] = pa1.x; sA[0][akc + 1][ar + 64] = pa1.y;
        sA[0][akc + 2][ar + 64] = pa1.z; sA[0][akc + 3][ar + 64] = pa1.w;
        *(float4*)&sB[0][bkk][bnc] = pb;
    }
    __syncthreads();

    int cur = 0;
#pragma unroll
    for (int it = 0; it < 8; it++) {
        if (it < 7) {
            int k0 = (it + 1) * 16;
            pa0 = (gr0 < M) ? *(const float4*)&A[(size_t)gr0 * 128 + k0 + akc] : make_float4(0, 0, 0, 0);
            pa1 = (gr1 < M) ? *(const float4*)&A[(size_t)gr1 * 128 + k0 + akc] : make_float4(0, 0, 0, 0);
            pb  = *(const float4*)&B[(size_t)(k0 + bkk) * 128 + col0 + bnc];
        }
#pragma unroll
        for (int kk = 0; kk < 16; kk++) {
            float4 a0 = *(float4*)&sA[cur][kk][ty * 8];
            float4 a1 = *(float4*)&sA[cur][kk][ty * 8 + 4];
            float4 b  = *(float4*)&sB[cur][kk][tx * 4];
            acc[0][0] += a0.x * b.x; acc[0][1] += a0.x * b.y; acc[0][2] += a0.x * b.z; acc[0][3] += a0.x * b.w;
            acc[1][0] += a0.y * b.x; acc[1][1] += a0.y * b.y; acc[1][2] += a0.y * b.z; acc[1][3] += a0.y * b.w;
            acc[2][0] += a0.z * b.x; acc[2][1] += a0.z * b.y; acc[2][2] += a0.z * b.z; acc[2][3] += a0.z * b.w;
            acc[3][0] += a0.w * b.x; acc[3][1] += a0.w * b.y; acc[3][2] += a0.w * b.z; acc[3][3] += a0.w * b.w;
            acc[4][0] += a1.x * b.x; acc[4][1] += a1.x * b.y; acc[4][2] += a1.x * b.z; acc[4][3] += a1.x * b.w;
            acc[5][0] += a1.y * b.x; acc[5][1] += a1.y * b.y; acc[5][2] += a1.y * b.z; acc[5][3] += a1.y * b.w;
            acc[6][0] += a1.z * b.x; acc[6][1] += a1.z * b.y; acc[6][2] += a1.z * b.z; acc[6][3] += a1.z * b.w;
            acc[7][0] += a1.w * b.x; acc[7][1] += a1.w * b.y; acc[7][2] += a1.w * b.z; acc[7][3] += a1.w * b.w;
        }
        if (it < 7) {
            int nb = cur ^ 1;
            sA[nb][akc + 0][ar] = pa0.x; sA[nb][akc + 1][ar] = pa0.y;
            sA[nb][akc + 2][ar] = pa0.z; sA[nb][akc + 3][ar] = pa0.w;
            sA[nb][akc + 0][ar + 64] = pa1.x; sA[nb][akc + 1][ar + 64] = pa1.y;
            sA[nb][akc + 2][ar + 64] = pa1.z; sA[nb][akc + 3][ar + 64] = pa1.w;
            *(float4*)&sB[nb][bkk][bnc] = pb;
            __syncthreads();
            cur = nb;
        }
    }

    float bv[4] = {0.f, 0.f, 0.f, 0.f};
    if (bias) {
#pragma unroll
        for (int j = 0; j < 4; j++) bv[j] = bias[col0 + tx * 4 + j];
    }
#pragma unroll
    for (int i = 0; i < 8; i++) {
        int row = row0 + ty * 8 + i;
        if (row >= M) continue;
        float v[4];
#pragma unroll
        for (int j = 0; j < 4; j++) {
            float c = acc[i][j] + bv[j];
            if (act == 1) c = elu1(c);
            v[j] = c;
        }
        *(float4*)&C[(size_t)row * 128 + col0 + tx * 4] =
            make_float4(v[0], v[1], v[2], v[3]);
    }
}

// ---------------- conv1 aggregation: warp per node, 8-head online softmax --
__global__ void conv1_agg(const float* __restrict__ att1, const float* __restrict__ b1) {
    int gw   = (blockIdx.x * blockDim.x + threadIdx.x) >> 5;
    int lane = threadIdx.x & 31;
    int d = gw;                                   // grid exact: 6250*8 = 50000
    const float* xlbase = g_xlxr;
    const float* xrbase = g_xlxr + (size_t)NN * 128;
    const float4 xr = *(const float4*)&xrbase[(size_t)d * 128 + lane * 4];
    const float4 av = *(const float4*)&att1[lane * 4]; // head=(lane>>2), ch=(lane&3)*4
    const float4 bb = *(const float4*)&b1[lane * 4];
    int beg = g_rowptr[d], end = g_rowptr[d + 1];

    float m = -INFINITY, s = 0.f;
    float ax = 0.f, ay = 0.f, az = 0.f, aw = 0.f;

    int src = g_csr[beg];
    float4 xl = *(const float4*)&xlbase[(size_t)src * 128 + lane * 4];
    for (int j = beg; j < end; j++) {
        float4 xln;
        if (j + 1 < end) {  // prefetch next row while computing current
            int nsrc = g_csr[j + 1];
            xln = *(const float4*)&xlbase[(size_t)nsrc * 128 + lane * 4];
        }
        float ex = lrelu(xl.x + xr.x);
        float ey = lrelu(xl.y + xr.y);
        float ez = lrelu(xl.z + xr.z);
        float ew = lrelu(xl.w + xr.w);
        float p = ex * av.x + ey * av.y + ez * av.z + ew * av.w;
        p += __shfl_xor_sync(0xffffffffu, p, 1);
        p += __shfl_xor_sync(0xffffffffu, p, 2);   // quad = one head
        float mn = fmaxf(m, p);
        float f  = __expf(m - mn);
        float wt = __expf(p - mn);
        s  = s * f + wt;
        ax = ax * f + xl.x * wt;
        ay = ay * f + xl.y * wt;
        az = az * f + xl.z * wt;
        aw = aw * f + xl.w * wt;
        m = mn;
        xl = xln;
    }
    float inv = 1.f / s;
    float4 o;
    o.x = elu1(ax * inv + bb.x);
    o.y = elu1(ay * inv + bb.y);
    o.z = elu1(az * inv + bb.z);
    o.w = elu1(aw * inv + bb.w);
    *(float4*)&g_h1[(size_t)d * 128 + lane * 4] = o;
}

// ---------------- conv2 transforms: [N,32] = h @ [Wl2|Wr2] -----------------
__global__ void conv2_transform(const float* __restrict__ h,
                                const float* __restrict__ Wl2,
                                const float* __restrict__ Wr2) {
    __shared__ float sw[128 * 32];
    __shared__ float sh[8][128];
    int t = threadIdx.x;
    for (int i = t; i < 128 * 16; i += 256) {
        int k = i >> 4, c = i & 15;
        sw[k * 32 + c]      = Wl2[i];
        sw[k * 32 + 16 + c] = Wr2[i];
    }
    int row0 = blockIdx.x * 8;
    for (int i = t; i < 8 * 128; i += 256) {
        int r = i >> 7;
        sh[r][i & 127] = h[(size_t)(row0 + r) * 128 + (i & 127)];
    }
    __syncthreads();
    int warp = t >> 5, lane = t & 31;
    int row = row0 + warp;                        // exact grid: 6250*8 = 50000
    float acc = 0.f;
#pragma unroll
    for (int k = 0; k < 128; k++) acc += sh[warp][k] * sw[k * 32 + lane];
    g_hlr[(size_t)row * 32 + lane] = acc;
}

// ---------------- conv2 aggregation + log_softmax: half-warp per node ------
__global__ void conv2_agg(const float* __restrict__ att2, const float* __restrict__ b2,
                          float* __restrict__ out) {
    int tid = blockIdx.x * blockDim.x + threadIdx.x;
    int d = tid >> 4;                             // exact grid: 3125*16 = 50000
    int l = tid & 15;
    unsigned hm = 0xFFFFu << (((threadIdx.x & 31) >> 4) * 16);  // own half-warp

    float xr = g_hlr[(size_t)d * 32 + 16 + l];
    float a  = att2[l];
    int beg = g_rowptr[d], end = g_rowptr[d + 1];

    float m = -INFINITY, s = 0.f, acc = 0.f;
    int src = g_csr[beg];
    float xl = g_hlr[(size_t)src * 32 + l];
    for (int j = beg; j < end; j++) {
        float xln = 0.f;
        if (j + 1 < end) {
            int nsrc = g_csr[j + 1];
            xln = g_hlr[(size_t)nsrc * 32 + l];
        }
        float p = lrelu(xl + xr) * a;
        p += __shfl_xor_sync(hm, p, 1);
        p += __shfl_xor_sync(hm, p, 2);
        p += __shfl_xor_sync(hm, p, 4);
        p += __shfl_xor_sync(hm, p, 8);
        float mn = fmaxf(m, p);
        float f  = __expf(m - mn);
        float w  = __expf(p - mn);
        s   = s * f + w;
        acc = acc * f + xl * w;
        m = mn;
        xl = xln;
    }
    float v = acc / s + b2[l];
    // log_softmax over the 16 channels (the 16 lanes of this half-warp)
    float mm = v;
#pragma unroll
    for (int k = 8; k >= 1; k >>= 1) mm = fmaxf(mm, __shfl_xor_sync(hm, mm, k));
    float pe = expf(v - mm);
    float ss = pe;
#pragma unroll
    for (int k = 8; k >= 1; k >>= 1) ss += __shfl_xor_sync(hm, ss, k);
    out[(size_t)d * 16 + l] = v - mm - logf(ss);
}

// ---------------- launch ----------------
extern "C" void kernel_launch(void* const* d_in, const int* in_sizes, int n_in,
                              void* d_out, int out_size) {
    const float* x    = (const float*)d_in[0];
    const void*  ei   = d_in[1];
    const float* Wl1  = (const float*)d_in[2];
    const float* Wr1  = (const float*)d_in[3];
    const float* att1 = (const float*)d_in[4];
    const float* b1   = (const float*)d_in[5];
    const float* Wk   = (const float*)d_in[6];
    const float* bk   = (const float*)d_in[7];
    const float* Wl2  = (const float*)d_in[8];
    const float* Wr2  = (const float*)d_in[9];
    const float* att2 = (const float*)d_in[10];
    const float* b2   = (const float*)d_in[11];
    float* out = (float*)d_out;

    float *xlxr, *h1, *h2;
    cudaGetSymbolAddress((void**)&xlxr, g_xlxr);
    cudaGetSymbolAddress((void**)&h1, g_h1);
    cudaGetSymbolAddress((void**)&h2, g_h2);
    float* xl = xlxr;
    float* xr = xlxr + (size_t)NN * 128;

    dim3 gx((NN + 127) / 128, 2);

    // 1: deg=0 + dtype detect
    init_detect<<<NB, 256>>>(ei);
    // 2: degrees (no self loops; accounted as deg+1 in the scan)
    degree_k<<<(EE + 255) / 256, 256>>>(ei);
    // 3: per-block partial sums
    scan_part<<<NB, 256>>>();
    // 4: conv1 xl transform  (profiled slot)
    gemm128t<<<gx, 256>>>(x, Wl1, xl, NN, nullptr, 0);
    // 5: conv1 xr transform
    gemm128t<<<gx, 256>>>(x, Wr1, xr, NN, nullptr, 0);
    // 6: scan partials
    scan_mid<<<1, 256>>>();
    // 7: rowptr + self-loop + cursor
    scan_add<<<NB, 256>>>();
    // 8: CSR scatter
    scatter_k<<<(EE + 255) / 256, 256>>>(ei);

    // 9: conv1 aggregation (+elu) -> g_h1
    conv1_agg<<<NN / 8, 256>>>(att1, b1);

    // 10-12: knowledge layers (elu fused)
    gemm128t<<<gx, 256>>>(h1, Wk,                 h2, NN, bk,       1);
    gemm128t<<<gx, 256>>>(h2, Wk + 128 * 128,     h1, NN, bk + 128, 1);
    gemm128t<<<gx, 256>>>(h1, Wk + 2 * 128 * 128, h2, NN, bk + 256, 1);

    // 13: conv2 transforms -> g_hlr
    conv2_transform<<<NN / 8, 256>>>(h2, Wl2, Wr2);

    // 14: conv2 aggregation + log_softmax -> out
    conv2_agg<<<NN / 16, 256>>>(att2, b2, out);
}

// round 4
// speedup vs baseline: 1.1818x; 1.0076x over previous
#include <cuda_runtime.h>
#include <math.h>

#define NN 50000
#define EE 800000
#define ET 850000   // EE + NN self loops
#define NB 196      // ceil(NN/256)

// ---------------- scratch (static device allocations only) ----------------
__device__ float g_xlxr[(size_t)NN * 256];   // [0:N*128)=xl dense, [N*128:)=xr dense
__device__ float g_h1[(size_t)NN * 128];
__device__ float g_h2[(size_t)NN * 128];
__device__ float g_hlr[(size_t)NN * 32];     // conv2: [0:16)=xl2, [16:32)=xr2
__device__ int   g_deg[NN];
__device__ int   g_rowptr[NN + 1];
__device__ int   g_cursor[NN];
__device__ int   g_csr[ET];
__device__ int   g_part[256];
__device__ int   g_is64;

__device__ __forceinline__ float lrelu(float x) { return x > 0.f ? x : 0.2f * x; }
__device__ __forceinline__ float elu1 (float x) { return x > 0.f ? x : expm1f(x); }

// ---------------- init deg=0 + dtype detect (block 0) ----------------------
__global__ void init_detect(const void* ei) {
    int i = blockIdx.x * blockDim.x + threadIdx.x;
    if (i < NN) g_deg[i] = 0;
    if (blockIdx.x == 0) {
        __shared__ int cnt;
        if (threadIdx.x == 0) cnt = 0;
        __syncthreads();
        const unsigned* p = (const unsigned*)ei;
        int nz = 0;
        for (int k = threadIdx.x; k < 2048; k += 256)
            if (p[2 * k + 1] != 0u) nz++;
        if (nz) atomicAdd(&cnt, nz);
        __syncthreads();
        if (threadIdx.x == 0) g_is64 = (cnt < 8) ? 1 : 0;
    }
}

__device__ __forceinline__ int edge_val(const void* ei, int idx, int is64) {
    if (is64) return (int)((const long long*)ei)[idx];
    return ((const int*)ei)[idx];
}

__global__ void degree_k(const void* ei) {
    int i = blockIdx.x * blockDim.x + threadIdx.x;
    if (i >= EE) return;
    int is64 = g_is64;
    int dst = edge_val(ei, EE + i, is64);
    atomicAdd(&g_deg[dst], 1);
}

// ---------------- parallel scan over (deg[i]+1) ----------------------------
__global__ void scan_part() {
    int t = threadIdx.x, lane = t & 31, w = t >> 5;
    int i = blockIdx.x * 256 + t;
    int v = (i < NN) ? g_deg[i] + 1 : 0;
#pragma unroll
    for (int off = 16; off >= 1; off >>= 1) v += __shfl_xor_sync(0xffffffffu, v, off);
    __shared__ int ws[8];
    if (lane == 0) ws[w] = v;
    __syncthreads();
    if (t == 0) {
        int s = 0;
#pragma unroll
        for (int k = 0; k < 8; k++) s += ws[k];
        g_part[blockIdx.x] = s;
    }
}

__global__ void scan_mid() {
    int t = threadIdx.x, lane = t & 31, w = t >> 5;
    int d = (t < NB) ? g_part[t] : 0;
    int v = d;
#pragma unroll
    for (int off = 1; off < 32; off <<= 1) {
        int u = __shfl_up_sync(0xffffffffu, v, off);
        if (lane >= off) v += u;
    }
    __shared__ int ws[8];
    if (lane == 31) ws[w] = v;
    __syncthreads();
    if (w == 0 && lane < 8) {
        int s = ws[lane];
#pragma unroll
        for (int off = 1; off < 8; off <<= 1) {
            int u = __shfl_up_sync(0xffu, s, off);
            if (lane >= off) s += u;
        }
        ws[lane] = s;
    }
    __syncthreads();
    int incl = v + (w > 0 ? ws[w - 1] : 0);
    if (t < NB) g_part[t] = incl - d;      // exclusive block offset
    if (t == 255) g_rowptr[NN] = incl;     // total (zeros beyond NB)
}

__global__ void scan_add() {
    int t = threadIdx.x, lane = t & 31, w = t >> 5;
    int i = blockIdx.x * 256 + t;
    int d = (i < NN) ? g_deg[i] + 1 : 0;
    int v = d;
#pragma unroll
    for (int off = 1; off < 32; off <<= 1) {
        int u = __shfl_up_sync(0xffffffffu, v, off);
        if (lane >= off) v += u;
    }
    __shared__ int ws[8];
    if (lane == 31) ws[w] = v;
    __syncthreads();
    if (w == 0 && lane < 8) {
        int s = ws[lane];
#pragma unroll
        for (int off = 1; off < 8; off <<= 1) {
            int u = __shfl_up_sync(0xffu, s, off);
            if (lane >= off) s += u;
        }
        ws[lane] = s;
    }
    __syncthreads();
    int excl = g_part[blockIdx.x] + v - d + (w > 0 ? ws[w - 1] : 0);
    if (i < NN) {
        g_rowptr[i] = excl;
        g_csr[excl] = i;          // self loop first
        g_cursor[i] = excl + 1;
    }
}

__global__ void scatter_k(const void* ei) {
    int i = blockIdx.x * blockDim.x + threadIdx.x;
    if (i >= EE) return;
    int is64 = g_is64;
    int s = edge_val(ei, i, is64);
    int d = edge_val(ei, EE + i, is64);
    int pos = atomicAdd(&g_cursor[d], 1);
    g_csr[pos] = s;
}

// ---------------- GEMM: C[M,128] = A[M,128] @ B[128,128] -------------------
// 128x64 tile, 256 threads, 8x4 micro-tile, K=128, double-buffered smem,
// forced 4 blocks/SM. grid=(ceil(M/128), ny). by<2 -> (B0,C0), else (B1,C1),
// col0=(by&1)*64. act: 0=none, 1=elu. bias may be null.
__global__ void __launch_bounds__(256, 4) gemm128t(
    const float* __restrict__ A,
    const float* __restrict__ B0, const float* __restrict__ B1,
    float* __restrict__ C0, float* __restrict__ C1, int M,
    const float* __restrict__ bias, int act) {
    __shared__ float sA[2][16][132];
    __shared__ float sB[2][16][64];
    int t  = threadIdx.x;
    int tx = t & 15, ty = t >> 4;
    int by = blockIdx.y;
    const float* B = (by < 2) ? B0 : B1;
    float*       C = (by < 2) ? C0 : C1;
    int row0 = blockIdx.x * 128;
    int col0 = (by & 1) * 64;

    int ar  = t >> 2;            // 0..63
    int akc = (t & 3) * 4;       // 0,4,8,12
    int bkk = t >> 4;            // 0..15
    int bnc = (t & 15) * 4;      // 0..60

    float acc[8][4];
#pragma unroll
    for (int i = 0; i < 8; i++)
#pragma unroll
        for (int j = 0; j < 4; j++) acc[i][j] = 0.f;

    float4 pa0, pa1, pb;
    int gr0 = row0 + ar, gr1 = row0 + ar + 64;

    // prologue: tile 0
    pa0 = (gr0 < M) ? *(const float4*)&A[(size_t)gr0 * 128 + akc] : make_float4(0, 0, 0, 0);
    pa1 = (gr1 < M) ? *(const float4*)&A[(size_t)gr1 * 128 + akc] : make_float4(0, 0, 0, 0);
    pb  = *(const float4*)&B[(size_t)bkk * 128 + col0 + bnc];
    {
        sA[0][akc + 0][ar] = pa0.x; sA[0][akc + 1][ar] = pa0.y;
        sA[0][akc + 2][ar] = pa0.z; sA[0][akc + 3][ar] = pa0.w;
        sA[0][akc + 0][ar + 64] = pa1.x; sA[0][akc + 1][ar + 64] = pa1.y;
        sA[0][akc + 2][ar + 64] = pa1.z; sA[0][akc + 3][ar + 64] = pa1.w;
        *(float4*)&sB[0][bkk][bnc] = pb;
    }
    __syncthreads();

    int cur = 0;
#pragma unroll
    for (int it = 0; it < 8; it++) {
        if (it < 7) {
            int k0 = (it + 1) * 16;
            pa0 = (gr0 < M) ? *(const float4*)&A[(size_t)gr0 * 128 + k0 + akc] : make_float4(0, 0, 0, 0);
            pa1 = (gr1 < M) ? *(const float4*)&A[(size_t)gr1 * 128 + k0 + akc] : make_float4(0, 0, 0, 0);
            pb  = *(const float4*)&B[(size_t)(k0 + bkk) * 128 + col0 + bnc];
        }
#pragma unroll
        for (int kk = 0; kk < 16; kk++) {
            float4 a0 = *(float4*)&sA[cur][kk][ty * 8];
            float4 a1 = *(float4*)&sA[cur][kk][ty * 8 + 4];
            float4 b  = *(float4*)&sB[cur][kk][tx * 4];
            acc[0][0] += a0.x * b.x; acc[0][1] += a0.x * b.y; acc[0][2] += a0.x * b.z; acc[0][3] += a0.x * b.w;
            acc[1][0] += a0.y * b.x; acc[1][1] += a0.y * b.y; acc[1][2] += a0.y * b.z; acc[1][3] += a0.y * b.w;
            acc[2][0] += a0.z * b.x; acc[2][1] += a0.z * b.y; acc[2][2] += a0.z * b.z; acc[2][3] += a0.z * b.w;
            acc[3][0] += a0.w * b.x; acc[3][1] += a0.w * b.y; acc[3][2] += a0.w * b.z; acc[3][3] += a0.w * b.w;
            acc[4][0] += a1.x * b.x; acc[4][1] += a1.x * b.y; acc[4][2] += a1.x * b.z; acc[4][3] += a1.x * b.w;
            acc[5][0] += a1.y * b.x; acc[5][1] += a1.y * b.y; acc[5][2] += a1.y * b.z; acc[5][3] += a1.y * b.w;
            acc[6][0] += a1.z * b.x; acc[6][1] += a1.z * b.y; acc[6][2] += a1.z * b.z; acc[6][3] += a1.z * b.w;
            acc[7][0] += a1.w * b.x; acc[7][1] += a1.w * b.y; acc[7][2] += a1.w * b.z; acc[7][3] += a1.w * b.w;
        }
        if (it < 7) {
            int nb = cur ^ 1;
            sA[nb][akc + 0][ar] = pa0.x; sA[nb][akc + 1][ar] = pa0.y;
            sA[nb][akc + 2][ar] = pa0.z; sA[nb][akc + 3][ar] = pa0.w;
            sA[nb][akc + 0][ar + 64] = pa1.x; sA[nb][akc + 1][ar + 64] = pa1.y;
            sA[nb][akc + 2][ar + 64] = pa1.z; sA[nb][akc + 3][ar + 64] = pa1.w;
            *(float4*)&sB[nb][bkk][bnc] = pb;
            __syncthreads();
            cur = nb;
        }
    }

    float bv[4] = {0.f, 0.f, 0.f, 0.f};
    if (bias) {
#pragma unroll
        for (int j = 0; j < 4; j++) bv[j] = bias[col0 + tx * 4 + j];
    }
#pragma unroll
    for (int i = 0; i < 8; i++) {
        int row = row0 + ty * 8 + i;
        if (row >= M) continue;
        float v[4];
#pragma unroll
        for (int j = 0; j < 4; j++) {
            float c = acc[i][j] + bv[j];
            if (act == 1) c = elu1(c);
            v[j] = c;
        }
        *(float4*)&C[(size_t)row * 128 + col0 + tx * 4] =
            make_float4(v[0], v[1], v[2], v[3]);
    }
}

// ---------------- conv1 aggregation: warp per node, 8-head online softmax --
__global__ void conv1_agg(const float* __restrict__ att1, const float* __restrict__ b1) {
    int gw   = (blockIdx.x * blockDim.x + threadIdx.x) >> 5;
    int lane = threadIdx.x & 31;
    int d = gw;                                   // grid exact: 6250*8 = 50000
    const float* xlbase = g_xlxr;
    const float* xrbase = g_xlxr + (size_t)NN * 128;
    const float4 xr = *(const float4*)&xrbase[(size_t)d * 128 + lane * 4];
    const float4 av = *(const float4*)&att1[lane * 4]; // head=(lane>>2), ch=(lane&3)*4
    const float4 bb = *(const float4*)&b1[lane * 4];
    int beg = g_rowptr[d], end = g_rowptr[d + 1];

    float m = -INFINITY, s = 0.f;
    float ax = 0.f, ay = 0.f, az = 0.f, aw = 0.f;

    // 2-deep prefetch pipeline
    float4 xl0, xl1;
    xl0 = *(const float4*)&xlbase[(size_t)g_csr[beg] * 128 + lane * 4];
    if (beg + 1 < end)
        xl1 = *(const float4*)&xlbase[(size_t)g_csr[beg + 1] * 128 + lane * 4];
    for (int j = beg; j < end; j++) {
        float4 xl2;
        if (j + 2 < end)
            xl2 = *(const float4*)&xlbase[(size_t)g_csr[j + 2] * 128 + lane * 4];
        float ex = lrelu(xl0.x + xr.x);
        float ey = lrelu(xl0.y + xr.y);
        float ez = lrelu(xl0.z + xr.z);
        float ew = lrelu(xl0.w + xr.w);
        float p = ex * av.x + ey * av.y + ez * av.z + ew * av.w;
        p += __shfl_xor_sync(0xffffffffu, p, 1);
        p += __shfl_xor_sync(0xffffffffu, p, 2);   // quad = one head
        float mn = fmaxf(m, p);
        float f  = __expf(m - mn);
        float wt = __expf(p - mn);
        s  = s * f + wt;
        ax = ax * f + xl0.x * wt;
        ay = ay * f + xl0.y * wt;
        az = az * f + xl0.z * wt;
        aw = aw * f + xl0.w * wt;
        m = mn;
        xl0 = xl1; xl1 = xl2;
    }
    float inv = 1.f / s;
    float4 o;
    o.x = elu1(ax * inv + bb.x);
    o.y = elu1(ay * inv + bb.y);
    o.z = elu1(az * inv + bb.z);
    o.w = elu1(aw * inv + bb.w);
    *(float4*)&g_h1[(size_t)d * 128 + lane * 4] = o;
}

// ---------------- conv2 transforms: [N,32] = h @ [Wl2|Wr2] -----------------
__global__ void conv2_transform(const float* __restrict__ h,
                                const float* __restrict__ Wl2,
                                const float* __restrict__ Wr2) {
    __shared__ float sw[128 * 32];
    __shared__ float sh[8][128];
    int t = threadIdx.x;
    for (int i = t; i < 128 * 16; i += 256) {
        int k = i >> 4, c = i & 15;
        sw[k * 32 + c]      = Wl2[i];
        sw[k * 32 + 16 + c] = Wr2[i];
    }
    int row0 = blockIdx.x * 8;
    for (int i = t; i < 8 * 128; i += 256) {
        int r = i >> 7;
        sh[r][i & 127] = h[(size_t)(row0 + r) * 128 + (i & 127)];
    }
    __syncthreads();
    int warp = t >> 5, lane = t & 31;
    int row = row0 + warp;                        // exact grid: 6250*8 = 50000
    float acc = 0.f;
#pragma unroll
    for (int k = 0; k < 128; k++) acc += sh[warp][k] * sw[k * 32 + lane];
    g_hlr[(size_t)row * 32 + lane] = acc;
}

// ---------------- conv2 aggregation + log_softmax: half-warp per node ------
__global__ void conv2_agg(const float* __restrict__ att2, const float* __restrict__ b2,
                          float* __restrict__ out) {
    int tid = blockIdx.x * blockDim.x + threadIdx.x;
    int d = tid >> 4;                             // exact grid: 3125*16 = 50000
    int l = tid & 15;
    unsigned hm = 0xFFFFu << (((threadIdx.x & 31) >> 4) * 16);  // own half-warp

    float xr = g_hlr[(size_t)d * 32 + 16 + l];
    float a  = att2[l];
    int beg = g_rowptr[d], end = g_rowptr[d + 1];

    float m = -INFINITY, s = 0.f, acc = 0.f;
    int src = g_csr[beg];
    float xl = g_hlr[(size_t)src * 32 + l];
    for (int j = beg; j < end; j++) {
        float xln = 0.f;
        if (j + 1 < end) {
            int nsrc = g_csr[j + 1];
            xln = g_hlr[(size_t)nsrc * 32 + l];
        }
        float p = lrelu(xl + xr) * a;
        p += __shfl_xor_sync(hm, p, 1);
        p += __shfl_xor_sync(hm, p, 2);
        p += __shfl_xor_sync(hm, p, 4);
        p += __shfl_xor_sync(hm, p, 8);
        float mn = fmaxf(m, p);
        float f  = __expf(m - mn);
        float w  = __expf(p - mn);
        s   = s * f + w;
        acc = acc * f + xl * w;
        m = mn;
        xl = xln;
    }
    float v = acc / s + b2[l];
    // log_softmax over the 16 channels (the 16 lanes of this half-warp)
    float mm = v;
#pragma unroll
    for (int k = 8; k >= 1; k >>= 1) mm = fmaxf(mm, __shfl_xor_sync(hm, mm, k));
    float pe = expf(v - mm);
    float ss = pe;
#pragma unroll
    for (int k = 8; k >= 1; k >>= 1) ss += __shfl_xor_sync(hm, ss, k);
    out[(size_t)d * 16 + l] = v - mm - logf(ss);
}

// ---------------- launch ----------------
extern "C" void kernel_launch(void* const* d_in, const int* in_sizes, int n_in,
                              void* d_out, int out_size) {
    const float* x    = (const float*)d_in[0];
    const void*  ei   = d_in[1];
    const float* Wl1  = (const float*)d_in[2];
    const float* Wr1  = (const float*)d_in[3];
    const float* att1 = (const float*)d_in[4];
    const float* b1   = (const float*)d_in[5];
    const float* Wk   = (const float*)d_in[6];
    const float* bk   = (const float*)d_in[7];
    const float* Wl2  = (const float*)d_in[8];
    const float* Wr2  = (const float*)d_in[9];
    const float* att2 = (const float*)d_in[10];
    const float* b2   = (const float*)d_in[11];
    float* out = (float*)d_out;

    float *xlxr, *h1, *h2;
    cudaGetSymbolAddress((void**)&xlxr, g_xlxr);
    cudaGetSymbolAddress((void**)&h1, g_h1);
    cudaGetSymbolAddress((void**)&h2, g_h2);
    float* xl = xlxr;
    float* xr = xlxr + (size_t)NN * 128;

    dim3 g2((NN + 127) / 128, 2);
    dim3 g4((NN + 127) / 128, 4);

    // 1: deg=0 + dtype detect
    init_detect<<<NB, 256>>>(ei);
    // 2: degrees (self loops accounted as deg+1 in the scan)
    degree_k<<<(EE + 255) / 256, 256>>>(ei);
    // 3: per-block partial sums
    scan_part<<<NB, 256>>>();
    // 4: conv1 xl+xr transforms, one launch (profiled slot)
    gemm128t<<<g4, 256>>>(x, Wl1, Wr1, xl, xr, NN, nullptr, 0);
    // 5: scan partials
    scan_mid<<<1, 256>>>();
    // 6: rowptr + self-loop + cursor
    scan_add<<<NB, 256>>>();
    // 7: CSR scatter
    scatter_k<<<(EE + 255) / 256, 256>>>(ei);

    // 8: conv1 aggregation (+elu) -> g_h1
    conv1_agg<<<NN / 8, 256>>>(att1, b1);

    // 9-11: knowledge layers (elu fused)
    gemm128t<<<g2, 256>>>(h1, Wk,                 nullptr, h2, nullptr, NN, bk,       1);
    gemm128t<<<g2, 256>>>(h2, Wk + 128 * 128,     nullptr, h1, nullptr, NN, bk + 128, 1);
    gemm128t<<<g2, 256>>>(h1, Wk + 2 * 128 * 128, nullptr, h2, nullptr, NN, bk + 256, 1);

    // 12: conv2 transforms -> g_hlr
    conv2_transform<<<NN / 8, 256>>>(h2, Wl2, Wr2);

    // 13: conv2 aggregation + log_softmax -> out
    conv2_agg<<<NN / 16, 256>>>(att2, b2, out);
}